// round 9
// baseline (speedup 1.0000x reference)
#include <cuda_runtime.h>
#include <cuda_bf16.h>
#include <cstdint>

#define T_LEN 50
typedef uint32_t u32;

// ---- mma.sync (legacy HMMA path on sm_103) ----
__device__ __forceinline__ void mma16816(float* d, u32 a0, u32 a1, u32 a2, u32 a3,
                                         u32 b0, u32 b1) {
    asm volatile(
        "mma.sync.aligned.m16n8k16.row.col.f32.bf16.bf16.f32 "
        "{%0,%1,%2,%3},{%4,%5,%6,%7},{%8,%9},{%0,%1,%2,%3};"
        : "+f"(d[0]), "+f"(d[1]), "+f"(d[2]), "+f"(d[3])
        : "r"(a0), "r"(a1), "r"(a2), "r"(a3), "r"(b0), "r"(b1));
}
// k8 x/bias tile, C=0 (chain head)
__device__ __forceinline__ void mma16808_z(float* d, u32 a0, u32 a1, u32 b0) {
    asm volatile(
        "mma.sync.aligned.m16n8k8.row.col.f32.bf16.bf16.f32 "
        "{%0,%1,%2,%3},{%4,%5},{%6},{%7,%8,%9,%10};"
        : "=f"(d[0]), "=f"(d[1]), "=f"(d[2]), "=f"(d[3])
        : "r"(a0), "r"(a1), "r"(b0),
          "f"(0.0f), "f"(0.0f), "f"(0.0f), "f"(0.0f));
}

// ---- bf16 helpers ----
__device__ __forceinline__ u32 bh_u(float v) {
    return (u32)__bfloat16_as_ushort(__float2bfloat16_rn(v));
}
__device__ __forceinline__ float bh_f(float v) {
    return __bfloat162float(__float2bfloat16_rn(v));
}
__device__ __forceinline__ float tanhapx(float x) {
    float r; asm("tanh.approx.f32 %0,%1;" : "=f"(r) : "f"(x)); return r;
}
__device__ __forceinline__ float trunc_hi(float v) {
    return __uint_as_float(__float_as_uint(v) & 0xFFFF0000u);
}
__device__ __forceinline__ u32 prmt_hi16(u32 a, u32 b) {
    u32 r; asm("prmt.b32 %0,%1,%2,%3;" : "=r"(r) : "r"(a), "r"(b), "n"(0x7632)); return r;
}
__device__ __forceinline__ u32 cvt_bf16x2(float hi_elem, float lo_elem) {
    u32 r; asm("cvt.rn.satfinite.bf16x2.f32 %0,%1,%2;" : "=r"(r) : "f"(hi_elem), "f"(lo_elem)); return r;
}

// CTA = 128 threads = 2 pairs. A pair (2 warps) shares 32 batches; warp wp
// computes gate tiles m = {2wp, 2wp+1} (units 16wp..16wp+15 = k-subtile wp).
// Per step each warp exchanges its new kt A-fragments with its partner via
// smem + one named barrier (double-buffered by t parity).
__global__ void __launch_bounds__(128, 4) lsnn_kernel(
    const float* __restrict__ x,     // [B, T, 2]
    const float* __restrict__ W_ih,  // [128, 2]
    const float* __restrict__ W_hh,  // [128, 32]
    const float* __restrict__ b_ih,  // [128]
    const float* __restrict__ b_hh,  // [128]
    const float* __restrict__ W_out, // [1, 32]
    const float* __restrict__ b_out, // [1]
    const float* __restrict__ h0,    // [B, 32]
    const float* __restrict__ c0,    // [B, 32]
    float* __restrict__ out)         // [B, 50]
{
    __shared__ __align__(16) u32 sbf[512 * 12];               // 24KB B-table
    __shared__ __align__(16) u32 sex[2][2][2][4][32][4];      // 16KB h exchange
    __shared__ float spo[2][2][2][2][2][8];                   // 2KB out partials
    __shared__ __align__(16) float csm[2][2][32][5][4];       // 10KB c state (slot 4 = pad)

    const int tid = threadIdx.x;

    // ---- B-table build: w[0..7] = Whh hi/lo fragments, w[8] = x/bias k8 frag ----
    for (int eid = tid; eid < 512; eid += 128) {
        const int jj = eid >> 5, ln = eid & 31;
        const int cc = ln & 3, gg = ln >> 2;
        const int m = jj >> 2, e = jj & 3;
        const int n = 32 * e + 8 * m + gg;
        const float sc = (e == 2) ? 1.0f : 0.5f;
        const float* wr = W_hh + n * 32;
        u32 w[12];
        const int ks = 2 * cc;
#pragma unroll
        for (int q = 0; q < 4; q++) {
            const int k0 = ks + 8 * q;
            float v0 = wr[k0] * sc, v1 = wr[k0 + 1] * sc;
            w[q]     = bh_u(v0) | (bh_u(v1) << 16);
            w[4 + q] = bh_u(v0 - bh_f(v0)) | (bh_u(v1 - bh_f(v1)) << 16);
        }
        {   // k8 x/bias B-frag: k rows = [W0h,W0h | W0l,W1h | W1h,W1l | bh,bl] by cc
            float W0 = W_ih[n * 2 + 0] * sc, W1 = W_ih[n * 2 + 1] * sc;
            float bv = (b_ih[n] + b_hh[n]) * sc;
            u32 xw;
            if (cc == 0)      { u32 u = bh_u(W0); xw = u | (u << 16); }
            else if (cc == 1) { xw = bh_u(W0 - bh_f(W0)) | (bh_u(W1) << 16); }
            else if (cc == 2) { xw = bh_u(W1) | (bh_u(W1 - bh_f(W1)) << 16); }
            else              { xw = bh_u(bv) | (bh_u(bv - bh_f(bv)) << 16); }
            w[8] = xw; w[9] = 0; w[10] = 0; w[11] = 0;
        }
#pragma unroll
        for (int q = 0; q < 12; q++) sbf[eid * 12 + q] = w[q];
    }
    __syncthreads();

    const int lane = tid & 31, wid = tid >> 5;
    const int p = wid >> 1, wp = wid & 1;
    const int c = lane & 3, g = lane >> 2;
    const long base = (long)blockIdx.x * 64 + p * 32;

    // ---- persistent A fragments (full K, both kt) ----
    u32 Ahi[2][2][4], Alo[2][2][4];
#pragma unroll
    for (int rb = 0; rb < 2; rb++)
#pragma unroll
        for (int kt = 0; kt < 2; kt++)
#pragma unroll
            for (int ms = 0; ms < 2; ms++)
#pragma unroll
                for (int row = 0; row < 2; row++) {
                    const long bb = base + rb * 16 + row * 8 + g;
                    const int u0 = 8 * (kt * 2 + ms) + 2 * c;
                    float hv0 = h0[bb * 32 + u0];
                    float hv1 = h0[bb * 32 + u0 + 1];
                    Ahi[rb][kt][ms * 2 + row] = bh_u(hv0) | (bh_u(hv1) << 16);
                    Alo[rb][kt][ms * 2 + row] =
                        bh_u(hv0 - bh_f(hv0)) | (bh_u(hv1 - bh_f(hv1)) << 16);
                }

    // ---- c state -> smem (own units only) ----
#pragma unroll
    for (int rb = 0; rb < 2; rb++)
#pragma unroll
        for (int ml = 0; ml < 2; ml++) {
            const int u0 = 8 * (wp * 2 + ml) + 2 * c;
            float4 v;
            v.x = c0[(base + rb * 16 + 0 + g) * 32 + u0];
            v.y = c0[(base + rb * 16 + 0 + g) * 32 + u0 + 1];
            v.z = c0[(base + rb * 16 + 8 + g) * 32 + u0];
            v.w = c0[(base + rb * 16 + 8 + g) * 32 + u0 + 1];
            *(float4*)&csm[p][wp][lane][rb * 2 + ml][0] = v;
        }

    float wo[2][2];
#pragma unroll
    for (int ml = 0; ml < 2; ml++) {
        wo[ml][0] = W_out[8 * (wp * 2 + ml) + 2 * c];
        wo[ml][1] = W_out[8 * (wp * 2 + ml) + 2 * c + 1];
    }
    const float bo = b_out[0];

    const float* xbase = x + (base + g) * (T_LEN * 2);
    float* obase = out + (base + g) * T_LEN;

    for (int t = 0; t < T_LEN; t++) {
        const int par = t & 1;

        // ---- x A-fragments (k8): [x0h,x0l | x0h,x1h | x1l,x1h | 1,1] by c ----
        u32 Ax[2][2];
#pragma unroll
        for (int rb = 0; rb < 2; rb++)
#pragma unroll
            for (int row = 0; row < 2; row++) {
                float2 xv = *(const float2*)(xbase + (rb * 16 + row * 8) * (T_LEN * 2) + 2 * t);
                u32 v;
                if (c == 0) {
                    v = (__float_as_uint(xv.x) >> 16) |
                        (bh_u(xv.x - trunc_hi(xv.x)) << 16);
                } else if (c == 1) {
                    v = (__float_as_uint(xv.x) >> 16) |
                        ((__float_as_uint(xv.y) >> 16) << 16);
                } else if (c == 2) {
                    v = bh_u(xv.y - trunc_hi(xv.y)) |
                        ((__float_as_uint(xv.y) >> 16) << 16);
                } else v = 0x3F803F80u;
                Ax[rb][row] = v;
            }

        u32 nAhi[2][4], nAlo[2][4];
        float oacc[2][2] = {{0.0f, 0.0f}, {0.0f, 0.0f}};

#pragma unroll
        for (int ml = 0; ml < 2; ml++) {
            const int mg = wp * 2 + ml;
            float D[2][4][4];
#pragma unroll
            for (int e = 0; e < 4; e++) {
                const u32* ent = sbf + (((mg * 4 + e) * 32) + lane) * 12;
                uint4 B0 = *(const uint4*)ent;
                uint4 B1 = *(const uint4*)(ent + 4);
                u32 B2x = ent[8];
#pragma unroll
                for (int rb = 0; rb < 2; rb++) {
                    mma16808_z(D[rb][e], Ax[rb][0], Ax[rb][1], B2x);
                    mma16816(D[rb][e], Ahi[rb][0][0], Ahi[rb][0][1], Ahi[rb][0][2], Ahi[rb][0][3], B0.x, B0.y);
                    mma16816(D[rb][e], Ahi[rb][1][0], Ahi[rb][1][1], Ahi[rb][1][2], Ahi[rb][1][3], B0.z, B0.w);
                    mma16816(D[rb][e], Alo[rb][0][0], Alo[rb][0][1], Alo[rb][0][2], Alo[rb][0][3], B0.x, B0.y);
                    mma16816(D[rb][e], Alo[rb][1][0], Alo[rb][1][1], Alo[rb][1][2], Alo[rb][1][3], B0.z, B0.w);
                    mma16816(D[rb][e], Ahi[rb][0][0], Ahi[rb][0][1], Ahi[rb][0][2], Ahi[rb][0][3], B1.x, B1.y);
                    mma16816(D[rb][e], Ahi[rb][1][0], Ahi[rb][1][1], Ahi[rb][1][2], Ahi[rb][1][3], B1.z, B1.w);
                }
            }
            // ---- epilogue for this m-tile ----
#pragma unroll
            for (int rb = 0; rb < 2; rb++) {
                float4 c4 = *(float4*)&csm[p][wp][lane][rb * 2 + ml][0];
                float cc4[4] = {c4.x, c4.y, c4.z, c4.w};
                float hn[2][2];
#pragma unroll
                for (int row = 0; row < 2; row++)
#pragma unroll
                    for (int b = 0; b < 2; b++) {
                        const int di = row * 2 + b;
                        float iv = fmaf(0.5f, tanhapx(D[rb][0][di]), 0.5f);
                        float fv = fmaf(0.5f, tanhapx(D[rb][1][di]), 0.5f);
                        float gv = tanhapx(D[rb][2][di]);
                        float ov = fmaf(0.5f, tanhapx(D[rb][3][di]), 0.5f);
                        float cn = fmaf(fv, cc4[di], iv * gv);
                        cc4[di] = cn;
                        float h = ov * tanhapx(cn);
                        hn[row][b] = h;
                        oacc[rb][row] = fmaf(h, wo[ml][b], oacc[rb][row]);
                    }
                *(float4*)&csm[p][wp][lane][rb * 2 + ml][0] =
                    make_float4(cc4[0], cc4[1], cc4[2], cc4[3]);
#pragma unroll
                for (int row = 0; row < 2; row++) {
                    u32 u0b = __float_as_uint(hn[row][0]);
                    u32 u1b = __float_as_uint(hn[row][1]);
                    nAhi[rb][ml * 2 + row] = prmt_hi16(u0b, u1b);
                    float l0 = hn[row][0] - trunc_hi(hn[row][0]);
                    float l1 = hn[row][1] - trunc_hi(hn[row][1]);
                    nAlo[rb][ml * 2 + row] = cvt_bf16x2(l1, l0);
                }
            }
        }

        // ---- reduce output partials over c within warp ----
#pragma unroll
        for (int rb = 0; rb < 2; rb++)
#pragma unroll
            for (int row = 0; row < 2; row++) {
                float o = oacc[rb][row];
                o += __shfl_xor_sync(0xffffffffu, o, 1);
                o += __shfl_xor_sync(0xffffffffu, o, 2);
                oacc[rb][row] = o;
            }

        // ---- exchange: own kt fragments + output partials ----
        *(uint4*)&sex[p][par][wp][0][lane][0] =
            make_uint4(nAhi[0][0], nAhi[0][1], nAhi[0][2], nAhi[0][3]);
        *(uint4*)&sex[p][par][wp][1][lane][0] =
            make_uint4(nAlo[0][0], nAlo[0][1], nAlo[0][2], nAlo[0][3]);
        *(uint4*)&sex[p][par][wp][2][lane][0] =
            make_uint4(nAhi[1][0], nAhi[1][1], nAhi[1][2], nAhi[1][3]);
        *(uint4*)&sex[p][par][wp][3][lane][0] =
            make_uint4(nAlo[1][0], nAlo[1][1], nAlo[1][2], nAlo[1][3]);
        if (c == 0) {
            spo[p][par][wp][0][0][g] = oacc[0][0];
            spo[p][par][wp][0][1][g] = oacc[0][1];
            spo[p][par][wp][1][0][g] = oacc[1][0];
            spo[p][par][wp][1][1][g] = oacc[1][1];
        }
        asm volatile("bar.sync %0, 64;" :: "r"(1 + p) : "memory");

        const int kx = wp ^ 1;
#pragma unroll
        for (int rb = 0; rb < 2; rb++)
#pragma unroll
            for (int q = 0; q < 4; q++) {
                Ahi[rb][wp][q] = nAhi[rb][q];
                Alo[rb][wp][q] = nAlo[rb][q];
            }
        {
            uint4 h0v = *(const uint4*)&sex[p][par][kx][0][lane][0];
            uint4 l0v = *(const uint4*)&sex[p][par][kx][1][lane][0];
            uint4 h1v = *(const uint4*)&sex[p][par][kx][2][lane][0];
            uint4 l1v = *(const uint4*)&sex[p][par][kx][3][lane][0];
            Ahi[0][kx][0] = h0v.x; Ahi[0][kx][1] = h0v.y; Ahi[0][kx][2] = h0v.z; Ahi[0][kx][3] = h0v.w;
            Alo[0][kx][0] = l0v.x; Alo[0][kx][1] = l0v.y; Alo[0][kx][2] = l0v.z; Alo[0][kx][3] = l0v.w;
            Ahi[1][kx][0] = h1v.x; Ahi[1][kx][1] = h1v.y; Ahi[1][kx][2] = h1v.z; Ahi[1][kx][3] = h1v.w;
            Alo[1][kx][0] = l1v.x; Alo[1][kx][1] = l1v.y; Alo[1][kx][2] = l1v.z; Alo[1][kx][3] = l1v.w;
        }

        // ---- store outputs: warp wp owns rb = wp ----
        if (c == 0) {
#pragma unroll
            for (int row = 0; row < 2; row++) {
                float o = oacc[wp][row] + spo[p][par][kx][wp][row][g] + bo;
                obase[(wp * 16 + row * 8) * T_LEN + t] = o;
            }
        }
    }
}

extern "C" void kernel_launch(void* const* d_in, const int* in_sizes, int n_in,
                              void* d_out, int out_size) {
    const float* x     = (const float*)d_in[0];
    const float* W_ih  = (const float*)d_in[1];
    const float* W_hh  = (const float*)d_in[2];
    const float* b_ih  = (const float*)d_in[3];
    const float* b_hh  = (const float*)d_in[4];
    const float* W_out = (const float*)d_in[5];
    const float* b_out = (const float*)d_in[6];
    const float* h0    = (const float*)d_in[7];
    const float* c0    = (const float*)d_in[8];
    float* out = (float*)d_out;

    // 32768 batches / 64 per CTA (2 pairs x 32 batches) = 512 CTAs
    lsnn_kernel<<<512, 128>>>(x, W_ih, W_hh, b_ih, b_hh,
                              W_out, b_out, h0, c0, out);
}

// round 10
// speedup vs baseline: 1.8000x; 1.8000x over previous
#include <cuda_runtime.h>
#include <cuda_fp16.h>
#include <cstdint>

#define T_LEN 50
typedef uint32_t u32;

// ---- fp16 mma.sync (legacy HMMA path on sm_103) ----
__device__ __forceinline__ void mma16816(float* d, u32 a0, u32 a1, u32 a2, u32 a3,
                                         u32 b0, u32 b1) {
    asm volatile(
        "mma.sync.aligned.m16n8k16.row.col.f32.f16.f16.f32 "
        "{%0,%1,%2,%3},{%4,%5,%6,%7},{%8,%9},{%0,%1,%2,%3};"
        : "+f"(d[0]), "+f"(d[1]), "+f"(d[2]), "+f"(d[3])
        : "r"(a0), "r"(a1), "r"(a2), "r"(a3), "r"(b0), "r"(b1));
}
// k8 x/bias tile, C=0 (chain head)
__device__ __forceinline__ void mma16808_z(float* d, u32 a0, u32 a1, u32 b0) {
    asm volatile(
        "mma.sync.aligned.m16n8k8.row.col.f32.f16.f16.f32 "
        "{%0,%1,%2,%3},{%4,%5},{%6},{%7,%8,%9,%10};"
        : "=f"(d[0]), "=f"(d[1]), "=f"(d[2]), "=f"(d[3])
        : "r"(a0), "r"(a1), "r"(b0),
          "f"(0.0f), "f"(0.0f), "f"(0.0f), "f"(0.0f));
}

// ---- fp16 helpers ----
__device__ __forceinline__ u32 pack_h2(float lo, float hi) {  // low16 = lo
    __half2 h = __floats2half2_rn(lo, hi);
    return *reinterpret_cast<u32*>(&h);
}
__device__ __forceinline__ float h_rnf(float v) {             // fp16 round-trip
    return __half2float(__float2half_rn(v));
}
__device__ __forceinline__ float tanhapx(float x) {
    float r; asm("tanh.approx.f32 %0,%1;" : "=f"(r) : "f"(x)); return r;
}

// x/bias k8 A-fragment word by c:
//  c0: (hi(x0), lo(x0))  c1: (hi(x0), hi(x1))  c2: (lo(x1), hi(x1))  c3: (1,1)
__device__ __forceinline__ u32 make_ax(float2 xv_, int c) {
    if (c == 0) return pack_h2(xv_.x, xv_.x - h_rnf(xv_.x));
    if (c == 1) return pack_h2(xv_.x, xv_.y);
    if (c == 2) return pack_h2(xv_.y - h_rnf(xv_.y), xv_.y);
    return 0x3C003C00u;
}

// R7 architecture: warp = 32 batches = 2 row-blocks of m16; thread (c=l%4,g=l/4)
// owns rows {g,g+8} per block, units {8m+2c,8m+2c+1}; recurrence fully in regs.
// Precision: A (h) single fp16; B (weights) fp16 hi+lo split -> 4 k16 + 1 k8
// MMAs per gate tile (was 6+1 with bf16 3-term). Gates prescaled: i,f,o by 0.5
// (sigmoid = 0.5 + 0.5*tanh), g by 1.0.
__global__ void __launch_bounds__(64, 4) lsnn_kernel(
    const float* __restrict__ x,     // [B, T, 2]
    const float* __restrict__ W_ih,  // [128, 2]
    const float* __restrict__ W_hh,  // [128, 32]
    const float* __restrict__ b_ih,  // [128]
    const float* __restrict__ b_hh,  // [128]
    const float* __restrict__ W_out, // [1, 32]
    const float* __restrict__ b_out, // [1]
    const float* __restrict__ h0,    // [B, 32]
    const float* __restrict__ c0,    // [B, 32]
    float* __restrict__ out)         // [B, 50]
{
    // B-table: 16 tiles x 32 lanes x 12 words (48B stride, LDS.128 conflict-free)
    // per entry: w[0..3]=Bhi (kt0 pair, kt1 pair), w[4..7]=Blo, w[8]=x/bias k8
    __shared__ __align__(16) u32 sbf[512 * 12];   // 24 KB

    const int tid = threadIdx.x;

    for (int eid = tid; eid < 512; eid += 64) {
        const int jj = eid >> 5, ln = eid & 31;
        const int cc = ln & 3, gg = ln >> 2;
        const int m = jj >> 2, e = jj & 3;
        const int n = 32 * e + 8 * m + gg;        // gate row in weights
        const float sc = (e == 2) ? 1.0f : 0.5f;
        const float* wr = W_hh + n * 32;
        u32 w[12];
        const int ks = 2 * cc;
#pragma unroll
        for (int q = 0; q < 4; q++) {
            const int k0 = ks + 8 * q;
            float v0 = wr[k0] * sc, v1 = wr[k0 + 1] * sc;
            w[q]     = pack_h2(v0, v1);
            w[4 + q] = pack_h2(v0 - h_rnf(v0), v1 - h_rnf(v1));
        }
        {   // k8 x/bias B-frag rows by cc: (W0h,W0h | W0l,W1h | W1h,W1l | bh,bl)
            float W0 = W_ih[n * 2 + 0] * sc, W1 = W_ih[n * 2 + 1] * sc;
            float bv = (b_ih[n] + b_hh[n]) * sc;
            u32 xw;
            if (cc == 0)      xw = pack_h2(W0, W0);
            else if (cc == 1) xw = pack_h2(W0 - h_rnf(W0), W1);
            else if (cc == 2) xw = pack_h2(W1, W1 - h_rnf(W1));
            else              xw = pack_h2(bv, bv - h_rnf(bv));
            w[8] = xw; w[9] = 0; w[10] = 0; w[11] = 0;
        }
#pragma unroll
        for (int q = 0; q < 12; q++) sbf[eid * 12 + q] = w[q];
    }
    __syncthreads();

    const int lane = tid & 31, warp = tid >> 5;
    const int c = lane & 3, g = lane >> 2;
    const long base = (long)blockIdx.x * 64 + warp * 32;

    const uint4* bpt = (const uint4*)(sbf + lane * 12);

    long brow[2][2];
    brow[0][0] = base + g;      brow[0][1] = base + g + 8;
    brow[1][0] = base + 16 + g; brow[1][1] = base + 24 + g;

    // ---- per-thread state ----
    float cst[2][16];
    u32 Ah[2][2][4];               // h as fp16 A-fragments [rb][kt][frag]
    float wo[8];
#pragma unroll
    for (int rb = 0; rb < 2; rb++)
#pragma unroll
        for (int m = 0; m < 4; m++)
#pragma unroll
            for (int row = 0; row < 2; row++) {
                const long bb = brow[rb][row];
                const int u0 = 8 * m + 2 * c;
                cst[rb][m * 4 + row * 2 + 0] = c0[bb * 32 + u0];
                cst[rb][m * 4 + row * 2 + 1] = c0[bb * 32 + u0 + 1];
                float hv0 = h0[bb * 32 + u0];
                float hv1 = h0[bb * 32 + u0 + 1];
                Ah[rb][m >> 1][(m & 1) * 2 + row] = pack_h2(hv0, hv1);
            }
#pragma unroll
    for (int m = 0; m < 4; m++) {
        wo[m * 2 + 0] = W_out[8 * m + 2 * c];
        wo[m * 2 + 1] = W_out[8 * m + 2 * c + 1];
    }
    const float bo = b_out[0];

    const float* xr[2][2];
    float2 xv[2][2];
#pragma unroll
    for (int rb = 0; rb < 2; rb++)
#pragma unroll
        for (int row = 0; row < 2; row++) {
            xr[rb][row] = x + brow[rb][row] * (T_LEN * 2);
            xv[rb][row] = *(const float2*)xr[rb][row];
        }

    for (int t = 0; t < T_LEN; t++) {
        // ---- x/bias A-fragments (k8) ----
        u32 Ax[2][2];
#pragma unroll
        for (int rb = 0; rb < 2; rb++) {
            Ax[rb][0] = make_ax(xv[rb][0], c);
            Ax[rb][1] = make_ax(xv[rb][1], c);
        }

        if (t + 1 < T_LEN) {        // prefetch next x
#pragma unroll
            for (int rb = 0; rb < 2; rb++)
#pragma unroll
                for (int row = 0; row < 2; row++)
                    xv[rb][row] = *(const float2*)(xr[rb][row] + 2 * (t + 1));
        }

        u32 nAh[2][2][4];
        float oacc[2][2] = {{0.0f, 0.0f}, {0.0f, 0.0f}};

#pragma unroll
        for (int m = 0; m < 4; m++) {
            float D[2][4][4];
#pragma unroll
            for (int e = 0; e < 4; e++) {
                const uint4* bp = bpt + (m * 4 + e) * 96;  // 32 lanes * 3 uint4
                uint4 B0 = bp[0];                          // Bhi: kt0 | kt1
                uint4 B1 = bp[1];                          // Blo: kt0 | kt1
                u32 B2 = ((const u32*)bp)[8];              // x/bias k8
#pragma unroll
                for (int rb = 0; rb < 2; rb++) {
                    mma16808_z(D[rb][e], Ax[rb][0], Ax[rb][1], B2);
                    mma16816(D[rb][e], Ah[rb][0][0], Ah[rb][0][1], Ah[rb][0][2], Ah[rb][0][3], B0.x, B0.y);
                    mma16816(D[rb][e], Ah[rb][1][0], Ah[rb][1][1], Ah[rb][1][2], Ah[rb][1][3], B0.z, B0.w);
                    mma16816(D[rb][e], Ah[rb][0][0], Ah[rb][0][1], Ah[rb][0][2], Ah[rb][0][3], B1.x, B1.y);
                    mma16816(D[rb][e], Ah[rb][1][0], Ah[rb][1][1], Ah[rb][1][2], Ah[rb][1][3], B1.z, B1.w);
                }
            }

            // ---- epilogue: gates -> c,h (thread-local) ----
#pragma unroll
            for (int rb = 0; rb < 2; rb++)
#pragma unroll
                for (int row = 0; row < 2; row++) {
                    float hn[2];
#pragma unroll
                    for (int b = 0; b < 2; b++) {
                        const int di = row * 2 + b;
                        float iv = fmaf(0.5f, tanhapx(D[rb][0][di]), 0.5f);
                        float fv = fmaf(0.5f, tanhapx(D[rb][1][di]), 0.5f);
                        float gv = tanhapx(D[rb][2][di]);
                        float ov = fmaf(0.5f, tanhapx(D[rb][3][di]), 0.5f);
                        const int ci = m * 4 + row * 2 + b;
                        float cn = fmaf(fv, cst[rb][ci], iv * gv);
                        cst[rb][ci] = cn;
                        hn[b] = ov * tanhapx(cn);
                        oacc[rb][row] = fmaf(hn[b], wo[m * 2 + b], oacc[rb][row]);
                    }
                    nAh[rb][m >> 1][(m & 1) * 2 + row] = pack_h2(hn[0], hn[1]);
                }
        }

#pragma unroll
        for (int rb = 0; rb < 2; rb++)
#pragma unroll
            for (int kt = 0; kt < 2; kt++)
#pragma unroll
                for (int q = 0; q < 4; q++)
                    Ah[rb][kt][q] = nAh[rb][kt][q];

        // ---- output projection: reduce over c (lanes xor 1,2) ----
#pragma unroll
        for (int rb = 0; rb < 2; rb++)
#pragma unroll
            for (int row = 0; row < 2; row++) {
                float o = oacc[rb][row];
                o += __shfl_xor_sync(0xffffffffu, o, 1);
                o += __shfl_xor_sync(0xffffffffu, o, 2);
                if (c == 0) out[brow[rb][row] * T_LEN + t] = o + bo;
            }
    }
}

extern "C" void kernel_launch(void* const* d_in, const int* in_sizes, int n_in,
                              void* d_out, int out_size) {
    const float* x     = (const float*)d_in[0];
    const float* W_ih  = (const float*)d_in[1];
    const float* W_hh  = (const float*)d_in[2];
    const float* b_ih  = (const float*)d_in[3];
    const float* b_hh  = (const float*)d_in[4];
    const float* W_out = (const float*)d_in[5];
    const float* b_out = (const float*)d_in[6];
    const float* h0    = (const float*)d_in[7];
    const float* c0    = (const float*)d_in[8];
    float* out = (float*)d_out;

    // 32768 batches / 64 per CTA (2 warps x 32) = 512 CTAs
    lsnn_kernel<<<512, 64>>>(x, W_ih, W_hh, b_ih, b_hh,
                             W_out, b_out, h0, c0, out);
}

// round 14
// speedup vs baseline: 1.8931x; 1.0517x over previous
#include <cuda_runtime.h>
#include <cuda_fp16.h>
#include <cstdint>

#define T_LEN 50
typedef uint32_t u32;

// ---- fp16 mma.sync (legacy HMMA path on sm_103) ----
__device__ __forceinline__ void mma16816(float* d, u32 a0, u32 a1, u32 a2, u32 a3,
                                         u32 b0, u32 b1) {
    asm volatile(
        "mma.sync.aligned.m16n8k16.row.col.f32.f16.f16.f32 "
        "{%0,%1,%2,%3},{%4,%5,%6,%7},{%8,%9},{%0,%1,%2,%3};"
        : "+f"(d[0]), "+f"(d[1]), "+f"(d[2]), "+f"(d[3])
        : "r"(a0), "r"(a1), "r"(a2), "r"(a3), "r"(b0), "r"(b1));
}
// k8 x/bias tile, C=0 (chain head)
__device__ __forceinline__ void mma16808_z(float* d, u32 a0, u32 a1, u32 b0) {
    asm volatile(
        "mma.sync.aligned.m16n8k8.row.col.f32.f16.f16.f32 "
        "{%0,%1,%2,%3},{%4,%5},{%6},{%7,%8,%9,%10};"
        : "=f"(d[0]), "=f"(d[1]), "=f"(d[2]), "=f"(d[3])
        : "r"(a0), "r"(a1), "r"(b0),
          "f"(0.0f), "f"(0.0f), "f"(0.0f), "f"(0.0f));
}

// ---- fp16 helpers ----
__device__ __forceinline__ u32 pack_h2(float lo, float hi) {  // low16 = lo
    __half2 h = __floats2half2_rn(lo, hi);
    return *reinterpret_cast<u32*>(&h);
}
__device__ __forceinline__ float h_rnf(float v) {
    return __half2float(__float2half_rn(v));
}
__device__ __forceinline__ u32 h2tanh(u32 x) {                // tanh.approx.f16x2
    u32 r; asm("tanh.approx.f16x2 %0,%1;" : "=r"(r) : "r"(x)); return r;
}

// x/bias k8 A-fragment word by c:
//  c0: (hi(x0), lo(x0))  c1: (hi(x0), hi(x1))  c2: (lo(x1), hi(x1))  c3: (1,1)
__device__ __forceinline__ u32 make_ax(float2 xv_, int c) {
    if (c == 0) return pack_h2(xv_.x, xv_.x - h_rnf(xv_.x));
    if (c == 1) return pack_h2(xv_.x, xv_.y);
    if (c == 2) return pack_h2(xv_.y - h_rnf(xv_.y), xv_.y);
    return 0x3C003C00u;
}

// R10 architecture: warp = 32 batches = 2 row-blocks of m16; thread (c=l%4,g=l/4)
// owns rows {g,g+8} per block, units {8m+2c,8m+2c+1}; recurrence fully in regs.
// Precision: A (h) fp16; B (weights) plain fp16 -> 2 k16 + 1 k8 per gate tile.
// Epilogue activations via tanh.approx.f16x2 on packed unit pairs; c stays fp32.
// Gates prescaled: i,f,o by 0.5 (sigmoid = 0.5 + 0.5*tanh), g by 1.0.
__global__ void __launch_bounds__(64, 4) lsnn_kernel(
    const float* __restrict__ x,     // [B, T, 2]
    const float* __restrict__ W_ih,  // [128, 2]
    const float* __restrict__ W_hh,  // [128, 32]
    const float* __restrict__ b_ih,  // [128]
    const float* __restrict__ b_hh,  // [128]
    const float* __restrict__ W_out, // [1, 32]
    const float* __restrict__ b_out, // [1]
    const float* __restrict__ h0,    // [B, 32]
    const float* __restrict__ c0,    // [B, 32]
    float* __restrict__ out)         // [B, 50]
{
    // B-table: 16 tiles x 32 lanes x 12 words (48B stride, LDS.128 conflict-free)
    // per entry: w[0..3]=Bhi (kt0 pair, kt1 pair), w[8]=x/bias k8
    __shared__ __align__(16) u32 sbf[512 * 12];   // 24 KB

    const int tid = threadIdx.x;

    for (int eid = tid; eid < 512; eid += 64) {
        const int jj = eid >> 5, ln = eid & 31;
        const int cc = ln & 3, gg = ln >> 2;
        const int m = jj >> 2, e = jj & 3;
        const int n = 32 * e + 8 * m + gg;        // gate row in weights
        const float sc = (e == 2) ? 1.0f : 0.5f;
        const float* wr = W_hh + n * 32;
        u32 w[12];
#pragma unroll
        for (int q = 0; q < 12; q++) w[q] = 0;
        const int ks = 2 * cc;
#pragma unroll
        for (int q = 0; q < 4; q++) {
            const int k0 = ks + 8 * q;
            w[q] = pack_h2(wr[k0] * sc, wr[k0 + 1] * sc);
        }
        {   // k8 x/bias B-frag rows by cc: (W0h,W0h | W0l,W1h | W1h,W1l | bh,bl)
            float W0 = W_ih[n * 2 + 0] * sc, W1 = W_ih[n * 2 + 1] * sc;
            float bv = (b_ih[n] + b_hh[n]) * sc;
            if (cc == 0)      w[8] = pack_h2(W0, W0);
            else if (cc == 1) w[8] = pack_h2(W0 - h_rnf(W0), W1);
            else if (cc == 2) w[8] = pack_h2(W1, W1 - h_rnf(W1));
            else              w[8] = pack_h2(bv, bv - h_rnf(bv));
        }
#pragma unroll
        for (int q = 0; q < 12; q++) sbf[eid * 12 + q] = w[q];
    }
    __syncthreads();

    const int lane = tid & 31, warp = tid >> 5;
    const int c = lane & 3, g = lane >> 2;
    const long base = (long)blockIdx.x * 64 + warp * 32;

    const uint4* bpt = (const uint4*)(sbf + lane * 12);

    long brow[2][2];
    brow[0][0] = base + g;      brow[0][1] = base + g + 8;
    brow[1][0] = base + 16 + g; brow[1][1] = base + 24 + g;

    // ---- per-thread state ----
    float cst[2][16];
    u32 Ah[2][2][4];               // h as fp16 A-fragments [rb][kt][frag]
    float wo[8];
#pragma unroll
    for (int rb = 0; rb < 2; rb++)
#pragma unroll
        for (int m = 0; m < 4; m++)
#pragma unroll
            for (int row = 0; row < 2; row++) {
                const long bb = brow[rb][row];
                const int u0 = 8 * m + 2 * c;
                cst[rb][m * 4 + row * 2 + 0] = c0[bb * 32 + u0];
                cst[rb][m * 4 + row * 2 + 1] = c0[bb * 32 + u0 + 1];
                Ah[rb][m >> 1][(m & 1) * 2 + row] =
                    pack_h2(h0[bb * 32 + u0], h0[bb * 32 + u0 + 1]);
            }
#pragma unroll
    for (int m = 0; m < 4; m++) {
        wo[m * 2 + 0] = W_out[8 * m + 2 * c];
        wo[m * 2 + 1] = W_out[8 * m + 2 * c + 1];
    }
    const float bo = b_out[0];
    const __half2 h05 = __float2half2_rn(0.5f);

    const float* xr[2][2];
    float2 xv[2][2];
#pragma unroll
    for (int rb = 0; rb < 2; rb++)
#pragma unroll
        for (int row = 0; row < 2; row++) {
            xr[rb][row] = x + brow[rb][row] * (T_LEN * 2);
            xv[rb][row] = *(const float2*)xr[rb][row];
        }

    for (int t = 0; t < T_LEN; t++) {
        // ---- x/bias A-fragments (k8) ----
        u32 Ax[2][2];
#pragma unroll
        for (int rb = 0; rb < 2; rb++) {
            Ax[rb][0] = make_ax(xv[rb][0], c);
            Ax[rb][1] = make_ax(xv[rb][1], c);
        }

        if (t + 1 < T_LEN) {        // prefetch next x
#pragma unroll
            for (int rb = 0; rb < 2; rb++)
#pragma unroll
                for (int row = 0; row < 2; row++)
                    xv[rb][row] = *(const float2*)(xr[rb][row] + 2 * (t + 1));
        }

        u32 nAh[2][2][4];
        float oacc[2][2] = {{0.0f, 0.0f}, {0.0f, 0.0f}};

#pragma unroll
        for (int m = 0; m < 4; m++) {
            float D[2][4][4];
#pragma unroll
            for (int e = 0; e < 4; e++) {
                const uint4* bp = bpt + (m * 4 + e) * 96;  // 32 lanes * 3 uint4
                uint4 B0 = bp[0];                          // Bhi: kt0 | kt1
                u32 B2 = ((const u32*)bp)[8];              // x/bias k8
#pragma unroll
                for (int rb = 0; rb < 2; rb++) {
                    mma16808_z(D[rb][e], Ax[rb][0], Ax[rb][1], B2);
                    mma16816(D[rb][e], Ah[rb][0][0], Ah[rb][0][1], Ah[rb][0][2], Ah[rb][0][3], B0.x, B0.y);
                    mma16816(D[rb][e], Ah[rb][1][0], Ah[rb][1][1], Ah[rb][1][2], Ah[rb][1][3], B0.z, B0.w);
                }
            }

            // ---- epilogue: packed f16x2 activations; c-update fp32 ----
#pragma unroll
            for (int rb = 0; rb < 2; rb++)
#pragma unroll
                for (int row = 0; row < 2; row++) {
                    const int d0 = row * 2;
                    u32 ti = h2tanh(pack_h2(D[rb][0][d0], D[rb][0][d0 + 1]));
                    u32 tf = h2tanh(pack_h2(D[rb][1][d0], D[rb][1][d0 + 1]));
                    u32 tg = h2tanh(pack_h2(D[rb][2][d0], D[rb][2][d0 + 1]));
                    u32 to = h2tanh(pack_h2(D[rb][3][d0], D[rb][3][d0 + 1]));
                    __half2 i2 = __hfma2(*(__half2*)&ti, h05, h05);
                    __half2 f2 = __hfma2(*(__half2*)&tf, h05, h05);
                    __half2 o2 = __hfma2(*(__half2*)&to, h05, h05);
                    float2 fi = __half22float2(i2);
                    float2 ff = __half22float2(f2);
                    float2 fg = __half22float2(*(__half2*)&tg);

                    const int ci = m * 4 + row * 2;
                    float cn0 = fmaf(ff.x, cst[rb][ci + 0], fi.x * fg.x);
                    float cn1 = fmaf(ff.y, cst[rb][ci + 1], fi.y * fg.y);
                    cst[rb][ci + 0] = cn0;
                    cst[rb][ci + 1] = cn1;

                    u32 tc = h2tanh(pack_h2(cn0, cn1));
                    __half2 h2v = __hmul2(o2, *(__half2*)&tc);
                    nAh[rb][m >> 1][(m & 1) * 2 + row] = *(u32*)&h2v;

                    float2 hf = __half22float2(h2v);
                    oacc[rb][row] = fmaf(hf.x, wo[m * 2 + 0], oacc[rb][row]);
                    oacc[rb][row] = fmaf(hf.y, wo[m * 2 + 1], oacc[rb][row]);
                }
        }

#pragma unroll
        for (int rb = 0; rb < 2; rb++)
#pragma unroll
            for (int kt = 0; kt < 2; kt++)
#pragma unroll
                for (int q = 0; q < 4; q++)
                    Ah[rb][kt][q] = nAh[rb][kt][q];

        // ---- output projection: reduce over c (lanes xor 1,2) ----
#pragma unroll
        for (int rb = 0; rb < 2; rb++)
#pragma unroll
            for (int row = 0; row < 2; row++) {
                float o = oacc[rb][row];
                o += __shfl_xor_sync(0xffffffffu, o, 1);
                o += __shfl_xor_sync(0xffffffffu, o, 2);
                if (c == 0) out[brow[rb][row] * T_LEN + t] = o + bo;
            }
    }
}

extern "C" void kernel_launch(void* const* d_in, const int* in_sizes, int n_in,
                              void* d_out, int out_size) {
    const float* x     = (const float*)d_in[0];
    const float* W_ih  = (const float*)d_in[1];
    const float* W_hh  = (const float*)d_in[2];
    const float* b_ih  = (const float*)d_in[3];
    const float* b_hh  = (const float*)d_in[4];
    const float* W_out = (const float*)d_in[5];
    const float* b_out = (const float*)d_in[6];
    const float* h0    = (const float*)d_in[7];
    const float* c0    = (const float*)d_in[8];
    float* out = (float*)d_out;

    // 32768 batches / 64 per CTA (2 warps x 32) = 512 CTAs
    lsnn_kernel<<<512, 64>>>(x, W_ih, W_hh, b_ih, b_hh,
                             W_out, b_out, h0, c0, out);
}

// round 15
// speedup vs baseline: 1.9810x; 1.0464x over previous
#include <cuda_runtime.h>
#include <cuda_fp16.h>
#include <cstdint>

#define T_LEN 50
typedef uint32_t u32;

// ---- fp16 mma.sync (legacy HMMA path on sm_103) ----
__device__ __forceinline__ void mma16816(float* d, u32 a0, u32 a1, u32 a2, u32 a3,
                                         u32 b0, u32 b1) {
    asm volatile(
        "mma.sync.aligned.m16n8k16.row.col.f32.f16.f16.f32 "
        "{%0,%1,%2,%3},{%4,%5,%6,%7},{%8,%9},{%0,%1,%2,%3};"
        : "+f"(d[0]), "+f"(d[1]), "+f"(d[2]), "+f"(d[3])
        : "r"(a0), "r"(a1), "r"(a2), "r"(a3), "r"(b0), "r"(b1));
}
// k8 x/bias tile, C=0 (chain head)
__device__ __forceinline__ void mma16808_z(float* d, u32 a0, u32 a1, u32 b0) {
    asm volatile(
        "mma.sync.aligned.m16n8k8.row.col.f32.f16.f16.f32 "
        "{%0,%1,%2,%3},{%4,%5},{%6},{%7,%8,%9,%10};"
        : "=f"(d[0]), "=f"(d[1]), "=f"(d[2]), "=f"(d[3])
        : "r"(a0), "r"(a1), "r"(b0),
          "f"(0.0f), "f"(0.0f), "f"(0.0f), "f"(0.0f));
}

// ---- fp16 helpers ----
__device__ __forceinline__ u32 pack_h2(float lo, float hi) {  // low16 = lo
    __half2 h = __floats2half2_rn(lo, hi);
    return *reinterpret_cast<u32*>(&h);
}
__device__ __forceinline__ float h_rnf(float v) {
    return __half2float(__float2half_rn(v));
}
__device__ __forceinline__ u32 h2tanh(u32 x) {                // tanh.approx.f16x2
    u32 r; asm("tanh.approx.f16x2 %0,%1;" : "=r"(r) : "r"(x)); return r;
}

// x/bias k8 A-fragment word by c:
//  c0: (hi(x0), lo(x0))  c1: (hi(x0), hi(x1))  c2: (lo(x1), hi(x1))  c3: (1,1)
__device__ __forceinline__ u32 make_ax(float2 xv_, int c) {
    if (c == 0) return pack_h2(xv_.x, xv_.x - h_rnf(xv_.x));
    if (c == 1) return pack_h2(xv_.x, xv_.y);
    if (c == 2) return pack_h2(xv_.y - h_rnf(xv_.y), xv_.y);
    return 0x3C003C00u;
}

// Occupancy-first variant: warp = 16 batches (ONE m16 row-block); thread
// (c=l%4,g=l/4) owns rows {g,g+8}, units {8m+2c,8m+2c+1}; recurrence fully in
// regs. 2048 warps -> 3.46/SMSP to hide the per-step dependency chain.
// Precision identical to R14: A fp16, B fp16, tanh.approx.f16x2, c fp32.
// Gates prescaled: i,f,o by 0.5 (sigmoid = 0.5 + 0.5*tanh), g by 1.0.
__global__ void __launch_bounds__(128, 4) lsnn_kernel(
    const float* __restrict__ x,     // [B, T, 2]
    const float* __restrict__ W_ih,  // [128, 2]
    const float* __restrict__ W_hh,  // [128, 32]
    const float* __restrict__ b_ih,  // [128]
    const float* __restrict__ b_hh,  // [128]
    const float* __restrict__ W_out, // [1, 32]
    const float* __restrict__ b_out, // [1]
    const float* __restrict__ h0,    // [B, 32]
    const float* __restrict__ c0,    // [B, 32]
    float* __restrict__ out)         // [B, 50]
{
    // B-table: 16 tiles x 32 lanes x 12 words (48B stride, LDS.128 conflict-free)
    // per entry: w[0..3]=B (kt0 pair, kt1 pair), w[8]=x/bias k8
    __shared__ __align__(16) u32 sbf[512 * 12];   // 24 KB

    const int tid = threadIdx.x;

    for (int eid = tid; eid < 512; eid += 128) {
        const int jj = eid >> 5, ln = eid & 31;
        const int cc = ln & 3, gg = ln >> 2;
        const int m = jj >> 2, e = jj & 3;
        const int n = 32 * e + 8 * m + gg;        // gate row in weights
        const float sc = (e == 2) ? 1.0f : 0.5f;
        const float* wr = W_hh + n * 32;
        u32 w[12];
#pragma unroll
        for (int q = 0; q < 12; q++) w[q] = 0;
        const int ks = 2 * cc;
#pragma unroll
        for (int q = 0; q < 4; q++) {
            const int k0 = ks + 8 * q;
            w[q] = pack_h2(wr[k0] * sc, wr[k0 + 1] * sc);
        }
        {   // k8 x/bias B-frag rows by cc: (W0h,W0h | W0l,W1h | W1h,W1l | bh,bl)
            float W0 = W_ih[n * 2 + 0] * sc, W1 = W_ih[n * 2 + 1] * sc;
            float bv = (b_ih[n] + b_hh[n]) * sc;
            if (cc == 0)      w[8] = pack_h2(W0, W0);
            else if (cc == 1) w[8] = pack_h2(W0 - h_rnf(W0), W1);
            else if (cc == 2) w[8] = pack_h2(W1, W1 - h_rnf(W1));
            else              w[8] = pack_h2(bv, bv - h_rnf(bv));
        }
#pragma unroll
        for (int q = 0; q < 12; q++) sbf[eid * 12 + q] = w[q];
    }
    __syncthreads();

    const int lane = tid & 31, warp = tid >> 5;
    const int c = lane & 3, g = lane >> 2;
    const long base = (long)blockIdx.x * 64 + warp * 16;

    const uint4* bpt = (const uint4*)(sbf + lane * 12);

    const long brow0 = base + g;        // row g
    const long brow1 = base + g + 8;    // row g+8

    // ---- per-thread state (one row-block) ----
    float cst[16];
    u32 Ah[2][4];                  // h as fp16 A-fragments [kt][frag]
    float wo[8];
#pragma unroll
    for (int m = 0; m < 4; m++)
#pragma unroll
        for (int row = 0; row < 2; row++) {
            const long bb = row ? brow1 : brow0;
            const int u0 = 8 * m + 2 * c;
            cst[m * 4 + row * 2 + 0] = c0[bb * 32 + u0];
            cst[m * 4 + row * 2 + 1] = c0[bb * 32 + u0 + 1];
            Ah[m >> 1][(m & 1) * 2 + row] =
                pack_h2(h0[bb * 32 + u0], h0[bb * 32 + u0 + 1]);
        }
#pragma unroll
    for (int m = 0; m < 4; m++) {
        wo[m * 2 + 0] = W_out[8 * m + 2 * c];
        wo[m * 2 + 1] = W_out[8 * m + 2 * c + 1];
    }
    const float bo = b_out[0];
    const __half2 h05 = __float2half2_rn(0.5f);

    const float* xr0 = x + brow0 * (T_LEN * 2);
    const float* xr1 = x + brow1 * (T_LEN * 2);
    float2 xv0 = *(const float2*)xr0;
    float2 xv1 = *(const float2*)xr1;

    for (int t = 0; t < T_LEN; t++) {
        // ---- x/bias A-fragment (k8) ----
        u32 Ax0 = make_ax(xv0, c);
        u32 Ax1 = make_ax(xv1, c);

        if (t + 1 < T_LEN) {        // prefetch next x
            xv0 = *(const float2*)(xr0 + 2 * (t + 1));
            xv1 = *(const float2*)(xr1 + 2 * (t + 1));
        }

        u32 nAh[2][4];
        float oacc0 = 0.0f, oacc1 = 0.0f;

#pragma unroll
        for (int m = 0; m < 4; m++) {
            float D[4][4];
#pragma unroll
            for (int e = 0; e < 4; e++) {
                const uint4* bp = bpt + (m * 4 + e) * 96;  // 32 lanes * 3 uint4
                uint4 B0 = bp[0];                          // B: kt0 | kt1
                u32 B2 = ((const u32*)bp)[8];              // x/bias k8
                mma16808_z(D[e], Ax0, Ax1, B2);
                mma16816(D[e], Ah[0][0], Ah[0][1], Ah[0][2], Ah[0][3], B0.x, B0.y);
                mma16816(D[e], Ah[1][0], Ah[1][1], Ah[1][2], Ah[1][3], B0.z, B0.w);
            }

            // ---- epilogue: packed f16x2 activations; c-update fp32 ----
#pragma unroll
            for (int row = 0; row < 2; row++) {
                const int d0 = row * 2;
                u32 ti = h2tanh(pack_h2(D[0][d0], D[0][d0 + 1]));
                u32 tf = h2tanh(pack_h2(D[1][d0], D[1][d0 + 1]));
                u32 tg = h2tanh(pack_h2(D[2][d0], D[2][d0 + 1]));
                u32 to = h2tanh(pack_h2(D[3][d0], D[3][d0 + 1]));
                __half2 i2 = __hfma2(*(__half2*)&ti, h05, h05);
                __half2 f2 = __hfma2(*(__half2*)&tf, h05, h05);
                __half2 o2 = __hfma2(*(__half2*)&to, h05, h05);
                float2 fi = __half22float2(i2);
                float2 ff = __half22float2(f2);
                float2 fg = __half22float2(*(__half2*)&tg);

                const int ci = m * 4 + row * 2;
                float cn0 = fmaf(ff.x, cst[ci + 0], fi.x * fg.x);
                float cn1 = fmaf(ff.y, cst[ci + 1], fi.y * fg.y);
                cst[ci + 0] = cn0;
                cst[ci + 1] = cn1;

                u32 tc = h2tanh(pack_h2(cn0, cn1));
                __half2 h2v = __hmul2(o2, *(__half2*)&tc);
                nAh[m >> 1][(m & 1) * 2 + row] = *(u32*)&h2v;

                float2 hf = __half22float2(h2v);
                float& oa = row ? oacc1 : oacc0;
                oa = fmaf(hf.x, wo[m * 2 + 0], oa);
                oa = fmaf(hf.y, wo[m * 2 + 1], oa);
            }
        }

#pragma unroll
        for (int kt = 0; kt < 2; kt++)
#pragma unroll
            for (int q = 0; q < 4; q++)
                Ah[kt][q] = nAh[kt][q];

        // ---- output projection: reduce over c (lanes xor 1,2) ----
        oacc0 += __shfl_xor_sync(0xffffffffu, oacc0, 1);
        oacc0 += __shfl_xor_sync(0xffffffffu, oacc0, 2);
        oacc1 += __shfl_xor_sync(0xffffffffu, oacc1, 1);
        oacc1 += __shfl_xor_sync(0xffffffffu, oacc1, 2);
        if (c == 0) {
            out[brow0 * T_LEN + t] = oacc0 + bo;
            out[brow1 * T_LEN + t] = oacc1 + bo;
        }
    }
}

extern "C" void kernel_launch(void* const* d_in, const int* in_sizes, int n_in,
                              void* d_out, int out_size) {
    const float* x     = (const float*)d_in[0];
    const float* W_ih  = (const float*)d_in[1];
    const float* W_hh  = (const float*)d_in[2];
    const float* b_ih  = (const float*)d_in[3];
    const float* b_hh  = (const float*)d_in[4];
    const float* W_out = (const float*)d_in[5];
    const float* b_out = (const float*)d_in[6];
    const float* h0    = (const float*)d_in[7];
    const float* c0    = (const float*)d_in[8];
    float* out = (float*)d_out;

    // 32768 batches / 64 per CTA (4 warps x 16 batches) = 512 CTAs
    lsnn_kernel<<<512, 128>>>(x, W_ih, W_hh, b_ih, b_hh,
                              W_out, b_out, h0, c0, out);
}